// round 3
// baseline (speedup 1.0000x reference)
#include <cuda_runtime.h>
#include <cuda_bf16.h>

#define BB 4
#define TT 2048
#define DD 1024
#define HH 16
#define HD 64

// Scratch (alloc-free rule: __device__ globals).
__device__ float g_Q[BB * TT * DD];
__device__ float g_K[BB * TT * DD];
__device__ float g_V[BB * TT * DD];
__device__ float g_O[BB * TT * DD];

// C[M,N] = A[M,K] * B[N,K]^T (+ bias), all row-major. 64x64 tile, BK=16,
// 256 threads, 4x4 micro-tile per thread.
__global__ __launch_bounds__(256) void gemm_nt(
    const float* __restrict__ A, const float* __restrict__ Bw,
    const float* __restrict__ bias, float* __restrict__ C,
    int M, int N, int K)
{
    __shared__ float As[16][64];
    __shared__ float Bs[16][64];
    const int tid = threadIdx.x;
    const int tx = tid & 15, ty = tid >> 4;
    const int m0 = blockIdx.y << 6, n0 = blockIdx.x << 6;
    const int lr = tid >> 2, lk = (tid & 3) << 2;
    const float* Ap = A + (size_t)(m0 + lr) * K + lk;
    const float* Bp = Bw + (size_t)(n0 + lr) * K + lk;

    float acc[4][4] = {};
    for (int k0 = 0; k0 < K; k0 += 16) {
        float4 a = *(const float4*)(Ap + k0);
        float4 b = *(const float4*)(Bp + k0);
        __syncthreads();   // previous tile's compute done before overwrite
        As[lk + 0][lr] = a.x; As[lk + 1][lr] = a.y;
        As[lk + 2][lr] = a.z; As[lk + 3][lr] = a.w;
        Bs[lk + 0][lr] = b.x; Bs[lk + 1][lr] = b.y;
        Bs[lk + 2][lr] = b.z; Bs[lk + 3][lr] = b.w;
        __syncthreads();
#pragma unroll
        for (int kk = 0; kk < 16; kk++) {
            float4 av = *(const float4*)&As[kk][ty << 2];
            float4 bv = *(const float4*)&Bs[kk][tx << 2];
            float am[4] = {av.x, av.y, av.z, av.w};
            float bn[4] = {bv.x, bv.y, bv.z, bv.w};
#pragma unroll
            for (int i = 0; i < 4; i++)
#pragma unroll
                for (int j = 0; j < 4; j++)
                    acc[i][j] = fmaf(am[i], bn[j], acc[i][j]);
        }
    }
#pragma unroll
    for (int i = 0; i < 4; i++) {
        const int m = m0 + (ty << 2) + i;
#pragma unroll
        for (int j = 0; j < 4; j++) {
            const int n = n0 + (tx << 2) + j;
            float v = acc[i][j];
            if (bias) v += bias[n];
            C[(size_t)m * N + n] = v;
        }
    }
}

// Flash attention, fp32. One CTA handles a 64-row Q tile of one (b,h);
// loops over 64-row K/V tiles with online softmax. Output written directly
// into concat layout O[(b*T+t)*D + h*64 + hd].
__global__ __launch_bounds__(256) void flash_attn(
    const float* __restrict__ Q, const float* __restrict__ K,
    const float* __restrict__ V, float* __restrict__ O)
{
    extern __shared__ float sm[];
    float* Qs = sm;                 // [64 k][64 m] (k-major)
    float* Ks = sm + 64 * 64;       // [64 k][64 n]
    float* Vs = sm + 2 * 64 * 64;   // [64 s][64 hd] (natural)
    float* Ps = sm + 3 * 64 * 64;   // [64 s][68 m]  (padded stride 68)

    const int bh = blockIdx.y;
    const int b = bh >> 4, h = bh & 15;
    const int t0 = blockIdx.x << 6;
    const int tid = threadIdx.x;
    const int tx = tid & 15, ty = tid >> 4;
    const int lr = tid >> 2, lc = (tid & 3) << 2;
    const float scale = 0.125f;  // 1/sqrt(64), folded into Q at load
    const size_t base = (size_t)b * TT * DD + h * HD;

    // Full 64x64 Q tile: each thread loads 4 float4s (row lr, cols lc+16c).
#pragma unroll
    for (int c = 0; c < 4; c++) {
        const int col = lc + (c << 4);
        float4 q = *(const float4*)&Q[base + (size_t)(t0 + lr) * DD + col];
        Qs[(col + 0) * 64 + lr] = q.x * scale;
        Qs[(col + 1) * 64 + lr] = q.y * scale;
        Qs[(col + 2) * 64 + lr] = q.z * scale;
        Qs[(col + 3) * 64 + lr] = q.w * scale;
    }

    float rO[4][4] = {};
    float mrow[4], lrow[4] = {};
#pragma unroll
    for (int i = 0; i < 4; i++) mrow[i] = -1e30f;

    for (int s0 = 0; s0 < TT; s0 += 64) {
        __syncthreads();  // prior PV reads of Ks/Vs done
#pragma unroll
        for (int c = 0; c < 4; c++) {
            const int col = lc + (c << 4);
            float4 kv = *(const float4*)&K[base + (size_t)(s0 + lr) * DD + col];
            Ks[(col + 0) * 64 + lr] = kv.x; Ks[(col + 1) * 64 + lr] = kv.y;
            Ks[(col + 2) * 64 + lr] = kv.z; Ks[(col + 3) * 64 + lr] = kv.w;
            float4 vv = *(const float4*)&V[base + (size_t)(s0 + lr) * DD + col];
            *(float4*)&Vs[lr * 64 + col] = vv;
        }
        __syncthreads();

        // S = (Q*scale) K^T   (64x64, 4x4 per thread)
        float rS[4][4] = {};
#pragma unroll 8
        for (int kk = 0; kk < 64; kk++) {
            float4 qv = *(const float4*)&Qs[kk * 64 + (ty << 2)];
            float4 kv = *(const float4*)&Ks[kk * 64 + (tx << 2)];
            float qm[4] = {qv.x, qv.y, qv.z, qv.w};
            float kn[4] = {kv.x, kv.y, kv.z, kv.w};
#pragma unroll
            for (int i = 0; i < 4; i++)
#pragma unroll
                for (int j = 0; j < 4; j++)
                    rS[i][j] = fmaf(qm[i], kn[j], rS[i][j]);
        }

        // online softmax (row state replicated across the 16 tx lanes)
#pragma unroll
        for (int i = 0; i < 4; i++) {
            float mx = fmaxf(fmaxf(rS[i][0], rS[i][1]), fmaxf(rS[i][2], rS[i][3]));
            mx = fmaxf(mx, __shfl_xor_sync(0xffffffffu, mx, 1));
            mx = fmaxf(mx, __shfl_xor_sync(0xffffffffu, mx, 2));
            mx = fmaxf(mx, __shfl_xor_sync(0xffffffffu, mx, 4));
            mx = fmaxf(mx, __shfl_xor_sync(0xffffffffu, mx, 8));
            const float mn = fmaxf(mrow[i], mx);
            const float alpha = __expf(mrow[i] - mn);
            mrow[i] = mn;
            float rsum = 0.f;
#pragma unroll
            for (int j = 0; j < 4; j++) {
                const float p = __expf(rS[i][j] - mn);
                rS[i][j] = p;
                rsum += p;
            }
            rsum += __shfl_xor_sync(0xffffffffu, rsum, 1);
            rsum += __shfl_xor_sync(0xffffffffu, rsum, 2);
            rsum += __shfl_xor_sync(0xffffffffu, rsum, 4);
            rsum += __shfl_xor_sync(0xffffffffu, rsum, 8);
            lrow[i] = lrow[i] * alpha + rsum;
#pragma unroll
            for (int j = 0; j < 4; j++) {
                rO[i][j] *= alpha;
                // P stored s-major-by-row, m along fast dim (stride-68 pad)
                Ps[((tx << 2) + j) * 68 + (ty << 2) + i] = rS[i][j];
            }
        }
        __syncthreads();

        // O += P V   (64x64 x 64)
#pragma unroll 8
        for (int ss = 0; ss < 64; ss++) {
            float4 pv = *(const float4*)&Ps[ss * 68 + (ty << 2)];
            float4 vv = *(const float4*)&Vs[ss * 64 + (tx << 2)];
            float pm[4] = {pv.x, pv.y, pv.z, pv.w};
            float vn[4] = {vv.x, vv.y, vv.z, vv.w};
#pragma unroll
            for (int i = 0; i < 4; i++)
#pragma unroll
                for (int j = 0; j < 4; j++)
                    rO[i][j] = fmaf(pm[i], vn[j], rO[i][j]);
        }
    }

#pragma unroll
    for (int i = 0; i < 4; i++) {
        const float inv = 1.0f / lrow[i];
#pragma unroll
        for (int j = 0; j < 4; j++) {
            O[base + (size_t)(t0 + (ty << 2) + i) * DD + (tx << 2) + j] =
                rO[i][j] * inv;
        }
    }
}

extern "C" void kernel_launch(void* const* d_in, const int* in_sizes, int n_in,
                              void* d_out, int out_size)
{
    const float* x  = (const float*)d_in[0];
    const float* Wq = (const float*)d_in[1];   // [H,HD,D] == [1024,1024] (out,in)
    const float* Wk = (const float*)d_in[2];
    const float* Wv = (const float*)d_in[3];
    const float* Wo = (const float*)d_in[4];   // [1024,1024] (out,in)
    const float* bo = (const float*)d_in[5];
    float* out = (float*)d_out;

    float *Qp, *Kp, *Vp, *Op;
    cudaGetSymbolAddress((void**)&Qp, g_Q);
    cudaGetSymbolAddress((void**)&Kp, g_K);
    cudaGetSymbolAddress((void**)&Vp, g_V);
    cudaGetSymbolAddress((void**)&Op, g_O);

    const int smem_attn = (3 * 64 * 64 + 64 * 68) * (int)sizeof(float);  // 66560
    cudaFuncSetAttribute(flash_attn, cudaFuncAttributeMaxDynamicSharedMemorySize,
                         smem_attn);

    dim3 gproj(DD / 64, (BB * TT) / 64);  // (16, 128)
    gemm_nt<<<gproj, 256>>>(x, Wq, nullptr, Qp, BB * TT, DD, DD);
    gemm_nt<<<gproj, 256>>>(x, Wk, nullptr, Kp, BB * TT, DD, DD);
    gemm_nt<<<gproj, 256>>>(x, Wv, nullptr, Vp, BB * TT, DD, DD);

    flash_attn<<<dim3(TT / 64, BB * HH), 256, smem_attn>>>(Qp, Kp, Vp, Op);

    gemm_nt<<<gproj, 256>>>(Op, Wo, bo, out, BB * TT, DD, DD);
}

// round 5
// speedup vs baseline: 1.4642x; 1.4642x over previous
#include <cuda_runtime.h>
#include <cuda_bf16.h>
#include <cstdint>

#define BB 4
#define TT 2048
#define DD 1024
#define HH 16
#define HD 64
#define MROWS (BB * TT)   // 8192

// ---------------- scratch (alloc-free rule: device globals) ----------------
__device__ float g_Q[MROWS * DD];
__device__ float g_K[MROWS * DD];
__device__ float g_V[MROWS * DD];
__device__ float g_O[MROWS * DD];
__device__ __nv_bfloat16 g_xh[MROWS * DD], g_xl[MROWS * DD];
__device__ __nv_bfloat16 g_oh[MROWS * DD], g_ol[MROWS * DD];
__device__ __nv_bfloat16 g_wh[4][DD * DD], g_wl[4][DD * DD];

// ---------------- helpers ----------------
__device__ __forceinline__ uint32_t smem_u32(const void* p) {
    uint32_t a;
    asm("{ .reg .u64 t; cvta.to.shared.u64 t, %1; cvt.u32.u64 %0, t; }"
        : "=r"(a) : "l"(p));
    return a;
}
#define SWZ(o) ((o) ^ (((o) >> 3) & 0x70))

__device__ __forceinline__ void cp16(uint32_t d, const void* s) {
    asm volatile("cp.async.cg.shared.global [%0], [%1], 16;"
                 :: "r"(d), "l"(s));
}
__device__ __forceinline__ void ldm_x4(uint32_t a, uint32_t* r) {
    asm volatile("ldmatrix.sync.aligned.m8n8.x4.shared.b16 {%0,%1,%2,%3}, [%4];"
                 : "=r"(r[0]), "=r"(r[1]), "=r"(r[2]), "=r"(r[3]) : "r"(a));
}
__device__ __forceinline__ void mma16816(float* d, const uint32_t* a,
                                         uint32_t b0, uint32_t b1) {
    asm volatile(
        "mma.sync.aligned.m16n8k16.row.col.f32.bf16.bf16.f32 "
        "{%0,%1,%2,%3},{%4,%5,%6,%7},{%8,%9},{%0,%1,%2,%3};"
        : "+f"(d[0]), "+f"(d[1]), "+f"(d[2]), "+f"(d[3])
        : "r"(a[0]), "r"(a[1]), "r"(a[2]), "r"(a[3]), "r"(b0), "r"(b1));
}

// ---------------- fp32 -> (bf16 hi, bf16 lo) split ----------------
__global__ __launch_bounds__(256) void split_hl(
    const float* __restrict__ in, __nv_bfloat16* __restrict__ hi,
    __nv_bfloat16* __restrict__ lo, int n4)
{
    int i = blockIdx.x * blockDim.x + threadIdx.x;
    if (i >= n4) return;
    float4 v = ((const float4*)in)[i];
    float f[4] = {v.x, v.y, v.z, v.w};
    unsigned short hs[4], ls[4];
#pragma unroll
    for (int j = 0; j < 4; j++) {
        __nv_bfloat16 hb = __float2bfloat16(f[j]);
        __nv_bfloat16 lb = __float2bfloat16(f[j] - __bfloat162float(hb));
        hs[j] = __bfloat16_as_ushort(hb);
        ls[j] = __bfloat16_as_ushort(lb);
    }
    ((ushort4*)hi)[i] = make_ushort4(hs[0], hs[1], hs[2], hs[3]);
    ((ushort4*)lo)[i] = make_ushort4(ls[0], ls[1], ls[2], ls[3]);
}

// ---------------- bf16x3 NT GEMM via mma.sync (HMMA) ----------------
// C[M,1024] = Ah*Bh^T + Ah*Bl^T + Al*Bh^T (+bias), fp32 accum in registers.
// 128x128 CTA tile, 8 warps (2m x 4n), each warp 64x32 (4x4 m16n8 frags).
// K in 16 blocks of 64; 2-stage cp.async double buffer, SW128 smem.
// smem tiles: (stage*4 + which)*16KB; which: 0=Ah 1=Al 2=Bh 3=Bl. 128KB total.
#define GEMM_SMEM (8 * 16384)

__global__ __launch_bounds__(256, 1) void gemm_bf16x3(
    const __nv_bfloat16* __restrict__ Ah, const __nv_bfloat16* __restrict__ Al,
    const __nv_bfloat16* __restrict__ Bh, const __nv_bfloat16* __restrict__ Bl,
    const float* __restrict__ bias, float* __restrict__ C)
{
    extern __shared__ char smem[];
    const int tid = threadIdx.x, wid = tid >> 5, lane = tid & 31;
    const uint32_t sb = smem_u32(smem);
    const int m0 = blockIdx.y << 7, n0 = blockIdx.x << 7;
    const int warp_m = (wid >> 2) << 6;   // 0 or 64
    const int warp_n = (wid & 3) << 5;    // 0,32,64,96

    const __nv_bfloat16* srcs[4] = {
        Ah + (size_t)m0 * DD, Al + (size_t)m0 * DD,
        Bh + (size_t)n0 * DD, Bl + (size_t)n0 * DD};

    auto tile = [&](int stg, int w) -> uint32_t {
        return sb + (uint32_t)(stg * 4 + w) * 16384;
    };
    auto load_stage = [&](int stg, int kb) {
#pragma unroll
        for (int t = 0; t < 4; t++) {
            const uint32_t tbase = tile(stg, t);
            const __nv_bfloat16* s = srcs[t] + kb * 64;
#pragma unroll
            for (int i = 0; i < 4; i++) {
                int c = tid + (i << 8);
                int r = c >> 3, col = c & 7;
                cp16(tbase + SWZ(r * 128 + col * 16),
                     s + (size_t)r * DD + col * 8);
            }
        }
        asm volatile("cp.async.commit_group;" ::: "memory");
    };

    // ldmatrix per-lane address components: sub-matrix = lane>>3
    const int sub = lane >> 3, r8 = lane & 7;
    const int lrow = ((sub & 1) << 3) + r8;   // row within 16-row group
    const int lbyte = (sub >> 1) << 4;        // 0 or 16 (k-half)

    float acc[4][4][4] = {};

    load_stage(0, 0);

    for (int kb = 0; kb < 16; kb++) {
        const int cur = kb & 1;
        if (kb < 15) load_stage(cur ^ 1, kb + 1);
        if (kb < 15)
            asm volatile("cp.async.wait_group 1;" ::: "memory");
        else
            asm volatile("cp.async.wait_group 0;" ::: "memory");
        __syncthreads();

        const uint32_t AhB = tile(cur, 0), AlB = tile(cur, 1);
        const uint32_t BhB = tile(cur, 2), BlB = tile(cur, 3);

#pragma unroll
        for (int ks = 0; ks < 4; ks++) {
            const int kbyte = (ks << 5) + lbyte;
            uint32_t ah[4][4], al[4][4], bh[2][4], bl[2][4];
#pragma unroll
            for (int mi = 0; mi < 4; mi++) {
                const uint32_t off = SWZ((warp_m + (mi << 4) + lrow) * 128 + kbyte);
                ldm_x4(AhB + off, ah[mi]);
                ldm_x4(AlB + off, al[mi]);
            }
#pragma unroll
            for (int nb = 0; nb < 2; nb++) {
                const uint32_t off = SWZ((warp_n + (nb << 4) + lrow) * 128 + kbyte);
                ldm_x4(BhB + off, bh[nb]);
                ldm_x4(BlB + off, bl[nb]);
            }
#pragma unroll
            for (int mi = 0; mi < 4; mi++)
#pragma unroll
                for (int ni = 0; ni < 4; ni++) {
                    const int nb = ni >> 1, nh = ni & 1;
                    mma16816(acc[mi][ni], ah[mi], bh[nb][nh], bh[nb][nh + 2]);
                    mma16816(acc[mi][ni], ah[mi], bl[nb][nh], bl[nb][nh + 2]);
                    mma16816(acc[mi][ni], al[mi], bh[nb][nh], bh[nb][nh + 2]);
                }
        }
        __syncthreads();
    }

    // epilogue
    const int gid = lane >> 2, tig = lane & 3;
#pragma unroll
    for (int mi = 0; mi < 4; mi++) {
#pragma unroll
        for (int ni = 0; ni < 4; ni++) {
            const int row = m0 + warp_m + (mi << 4) + gid;
            const int col = n0 + warp_n + (ni << 3) + (tig << 1);
            float2 v0 = make_float2(acc[mi][ni][0], acc[mi][ni][1]);
            float2 v1 = make_float2(acc[mi][ni][2], acc[mi][ni][3]);
            if (bias) {
                float2 bv = *(const float2*)&bias[col];
                v0.x += bv.x; v0.y += bv.y;
                v1.x += bv.x; v1.y += bv.y;
            }
            *(float2*)&C[(size_t)row * DD + col] = v0;
            *(float2*)&C[(size_t)(row + 8) * DD + col] = v1;
        }
    }
}

// ---------------- flash attention (fp32, unchanged from R3) ----------------
__global__ __launch_bounds__(256) void flash_attn(
    const float* __restrict__ Q, const float* __restrict__ K,
    const float* __restrict__ V, float* __restrict__ O)
{
    extern __shared__ float sm[];
    float* Qs = sm;                 // [64 k][64 m]
    float* Ks = sm + 64 * 64;       // [64 k][64 n]
    float* Vs = sm + 2 * 64 * 64;   // [64 s][64 hd]
    float* Ps = sm + 3 * 64 * 64;   // [64 s][68 m]

    const int bh = blockIdx.y;
    const int b = bh >> 4, h = bh & 15;
    const int t0 = blockIdx.x << 6;
    const int tid = threadIdx.x;
    const int tx = tid & 15, ty = tid >> 4;
    const int lr = tid >> 2, lc = (tid & 3) << 2;
    const float scale = 0.125f;
    const size_t base = (size_t)b * TT * DD + h * HD;

#pragma unroll
    for (int c = 0; c < 4; c++) {
        const int col = lc + (c << 4);
        float4 q = *(const float4*)&Q[base + (size_t)(t0 + lr) * DD + col];
        Qs[(col + 0) * 64 + lr] = q.x * scale;
        Qs[(col + 1) * 64 + lr] = q.y * scale;
        Qs[(col + 2) * 64 + lr] = q.z * scale;
        Qs[(col + 3) * 64 + lr] = q.w * scale;
    }

    float rO[4][4] = {};
    float mrow[4], lrow[4] = {};
#pragma unroll
    for (int i = 0; i < 4; i++) mrow[i] = -1e30f;

    for (int s0 = 0; s0 < TT; s0 += 64) {
        __syncthreads();
#pragma unroll
        for (int c = 0; c < 4; c++) {
            const int col = lc + (c << 4);
            float4 kv = *(const float4*)&K[base + (size_t)(s0 + lr) * DD + col];
            Ks[(col + 0) * 64 + lr] = kv.x; Ks[(col + 1) * 64 + lr] = kv.y;
            Ks[(col + 2) * 64 + lr] = kv.z; Ks[(col + 3) * 64 + lr] = kv.w;
            float4 vv = *(const float4*)&V[base + (size_t)(s0 + lr) * DD + col];
            *(float4*)&Vs[lr * 64 + col] = vv;
        }
        __syncthreads();

        float rS[4][4] = {};
#pragma unroll 8
        for (int kk = 0; kk < 64; kk++) {
            float4 qv = *(const float4*)&Qs[kk * 64 + (ty << 2)];
            float4 kv = *(const float4*)&Ks[kk * 64 + (tx << 2)];
            float qm[4] = {qv.x, qv.y, qv.z, qv.w};
            float kn[4] = {kv.x, kv.y, kv.z, kv.w};
#pragma unroll
            for (int i = 0; i < 4; i++)
#pragma unroll
                for (int j = 0; j < 4; j++)
                    rS[i][j] = fmaf(qm[i], kn[j], rS[i][j]);
        }

#pragma unroll
        for (int i = 0; i < 4; i++) {
            float mx = fmaxf(fmaxf(rS[i][0], rS[i][1]), fmaxf(rS[i][2], rS[i][3]));
            mx = fmaxf(mx, __shfl_xor_sync(0xffffffffu, mx, 1));
            mx = fmaxf(mx, __shfl_xor_sync(0xffffffffu, mx, 2));
            mx = fmaxf(mx, __shfl_xor_sync(0xffffffffu, mx, 4));
            mx = fmaxf(mx, __shfl_xor_sync(0xffffffffu, mx, 8));
            const float mn = fmaxf(mrow[i], mx);
            const float alpha = __expf(mrow[i] - mn);
            mrow[i] = mn;
            float rsum = 0.f;
#pragma unroll
            for (int j = 0; j < 4; j++) {
                const float p = __expf(rS[i][j] - mn);
                rS[i][j] = p;
                rsum += p;
            }
            rsum += __shfl_xor_sync(0xffffffffu, rsum, 1);
            rsum += __shfl_xor_sync(0xffffffffu, rsum, 2);
            rsum += __shfl_xor_sync(0xffffffffu, rsum, 4);
            rsum += __shfl_xor_sync(0xffffffffu, rsum, 8);
            lrow[i] = lrow[i] * alpha + rsum;
#pragma unroll
            for (int j = 0; j < 4; j++) {
                rO[i][j] *= alpha;
                Ps[((tx << 2) + j) * 68 + (ty << 2) + i] = rS[i][j];
            }
        }
        __syncthreads();

#pragma unroll 8
        for (int ss = 0; ss < 64; ss++) {
            float4 pv = *(const float4*)&Ps[ss * 68 + (ty << 2)];
            float4 vv = *(const float4*)&Vs[ss * 64 + (tx << 2)];
            float pm[4] = {pv.x, pv.y, pv.z, pv.w};
            float vn[4] = {vv.x, vv.y, vv.z, vv.w};
#pragma unroll
            for (int i = 0; i < 4; i++)
#pragma unroll
                for (int j = 0; j < 4; j++)
                    rO[i][j] = fmaf(pm[i], vn[j], rO[i][j]);
        }
    }

#pragma unroll
    for (int i = 0; i < 4; i++) {
        const float inv = 1.0f / lrow[i];
#pragma unroll
        for (int j = 0; j < 4; j++) {
            O[base + (size_t)(t0 + (ty << 2) + i) * DD + (tx << 2) + j] =
                rO[i][j] * inv;
        }
    }
}

// ---------------- launcher ----------------
extern "C" void kernel_launch(void* const* d_in, const int* in_sizes, int n_in,
                              void* d_out, int out_size)
{
    const float* x  = (const float*)d_in[0];
    const float* Wq = (const float*)d_in[1];
    const float* Wk = (const float*)d_in[2];
    const float* Wv = (const float*)d_in[3];
    const float* Wo = (const float*)d_in[4];
    const float* bo = (const float*)d_in[5];
    float* out = (float*)d_out;

    float *Qp, *Kp, *Vp, *Op;
    cudaGetSymbolAddress((void**)&Qp, g_Q);
    cudaGetSymbolAddress((void**)&Kp, g_K);
    cudaGetSymbolAddress((void**)&Vp, g_V);
    cudaGetSymbolAddress((void**)&Op, g_O);
    __nv_bfloat16 *xh, *xl, *oh, *ol, *wh, *wl;
    cudaGetSymbolAddress((void**)&xh, g_xh);
    cudaGetSymbolAddress((void**)&xl, g_xl);
    cudaGetSymbolAddress((void**)&oh, g_oh);
    cudaGetSymbolAddress((void**)&ol, g_ol);
    cudaGetSymbolAddress((void**)&wh, g_wh);
    cudaGetSymbolAddress((void**)&wl, g_wl);

    cudaFuncSetAttribute(gemm_bf16x3,
                         cudaFuncAttributeMaxDynamicSharedMemorySize, GEMM_SMEM);
    const int smem_attn = (3 * 64 * 64 + 64 * 68) * (int)sizeof(float);
    cudaFuncSetAttribute(flash_attn,
                         cudaFuncAttributeMaxDynamicSharedMemorySize, smem_attn);

    const int n4x = MROWS * DD / 4;
    const int n4w = DD * DD / 4;
    split_hl<<<n4x / 256, 256>>>(x, xh, xl, n4x);
    const float* Ws[4] = {Wq, Wk, Wv, Wo};
    for (int i = 0; i < 4; i++)
        split_hl<<<n4w / 256, 256>>>(Ws[i], wh + (size_t)i * DD * DD,
                                     wl + (size_t)i * DD * DD, n4w);

    dim3 gg(DD / 128, MROWS / 128);  // (8, 64)
    gemm_bf16x3<<<gg, 256, GEMM_SMEM>>>(xh, xl, wh + 0 * (size_t)DD * DD,
                                        wl + 0 * (size_t)DD * DD, nullptr, Qp);
    gemm_bf16x3<<<gg, 256, GEMM_SMEM>>>(xh, xl, wh + 1 * (size_t)DD * DD,
                                        wl + 1 * (size_t)DD * DD, nullptr, Kp);
    gemm_bf16x3<<<gg, 256, GEMM_SMEM>>>(xh, xl, wh + 2 * (size_t)DD * DD,
                                        wl + 2 * (size_t)DD * DD, nullptr, Vp);

    flash_attn<<<dim3(TT / 64, BB * HH), 256, smem_attn>>>(Qp, Kp, Vp, Op);

    split_hl<<<n4x / 256, 256>>>(Op, oh, ol, n4x);
    gemm_bf16x3<<<gg, 256, GEMM_SMEM>>>(oh, ol, wh + 3 * (size_t)DD * DD,
                                        wl + 3 * (size_t)DD * DD, bo, out);
}

// round 6
// speedup vs baseline: 3.6660x; 2.5037x over previous
#include <cuda_runtime.h>
#include <cuda_bf16.h>
#include <cuda_fp16.h>
#include <cstdint>

#define BB 4
#define TT 2048
#define DD 1024
#define HH 16
#define HD 64
#define MROWS (BB * TT)   // 8192

// ---------------- scratch (alloc-free rule: device globals) ----------------
__device__ __nv_bfloat16 g_xh[MROWS * DD], g_xl[MROWS * DD];
__device__ __nv_bfloat16 g_wh[4][DD * DD], g_wl[4][DD * DD];
__device__ __half        g_q16[MROWS * DD], g_k16[MROWS * DD];
__device__ __nv_bfloat16 g_vh[MROWS * DD], g_vl[MROWS * DD];
__device__ __nv_bfloat16 g_oh[MROWS * DD], g_ol[MROWS * DD];

// ---------------- helpers ----------------
__device__ __forceinline__ uint32_t smem_u32(const void* p) {
    uint32_t a;
    asm("{ .reg .u64 t; cvta.to.shared.u64 t, %1; cvt.u32.u64 %0, t; }"
        : "=r"(a) : "l"(p));
    return a;
}
#define SWZ(o) ((o) ^ (((o) >> 3) & 0x70))

__device__ __forceinline__ void cp16(uint32_t d, const void* s) {
    asm volatile("cp.async.cg.shared.global [%0], [%1], 16;"
                 :: "r"(d), "l"(s));
}
__device__ __forceinline__ void ldm_x4(uint32_t a, uint32_t* r) {
    asm volatile("ldmatrix.sync.aligned.m8n8.x4.shared.b16 {%0,%1,%2,%3}, [%4];"
                 : "=r"(r[0]), "=r"(r[1]), "=r"(r[2]), "=r"(r[3]) : "r"(a));
}
__device__ __forceinline__ void ldm_x4t(uint32_t a, uint32_t* r) {
    asm volatile("ldmatrix.sync.aligned.m8n8.x4.trans.shared.b16 {%0,%1,%2,%3}, [%4];"
                 : "=r"(r[0]), "=r"(r[1]), "=r"(r[2]), "=r"(r[3]) : "r"(a));
}
__device__ __forceinline__ void mma_bf16(float* d, const uint32_t* a,
                                         uint32_t b0, uint32_t b1) {
    asm volatile(
        "mma.sync.aligned.m16n8k16.row.col.f32.bf16.bf16.f32 "
        "{%0,%1,%2,%3},{%4,%5,%6,%7},{%8,%9},{%0,%1,%2,%3};"
        : "+f"(d[0]), "+f"(d[1]), "+f"(d[2]), "+f"(d[3])
        : "r"(a[0]), "r"(a[1]), "r"(a[2]), "r"(a[3]), "r"(b0), "r"(b1));
}
__device__ __forceinline__ void mma_f16(float* d, const uint32_t* a,
                                        uint32_t b0, uint32_t b1) {
    asm volatile(
        "mma.sync.aligned.m16n8k16.row.col.f32.f16.f16.f32 "
        "{%0,%1,%2,%3},{%4,%5,%6,%7},{%8,%9},{%0,%1,%2,%3};"
        : "+f"(d[0]), "+f"(d[1]), "+f"(d[2]), "+f"(d[3])
        : "r"(a[0]), "r"(a[1]), "r"(a[2]), "r"(a[3]), "r"(b0), "r"(b1));
}
// pack {lo, hi} floats into bf16x2 (first PTX src -> high half)
__device__ __forceinline__ uint32_t packbf(float lo, float hi) {
    uint32_t r;
    asm("cvt.rn.bf16x2.f32 %0, %1, %2;" : "=r"(r) : "f"(hi), "f"(lo));
    return r;
}
// fast exp on FMA/ALU pipes (avoids MUFU); ~2e-6 rel for x <= 0
__device__ __forceinline__ float fexp(float x) {
    const float l2e = 1.4426950408889634f;
    x = fmaxf(x, -87.0f);
    float t = fmaf(x, l2e, 12582912.0f);       // round-to-nearest via magic
    float i = t - 12582912.0f;
    float f = fmaf(x, l2e, -i);                // f in [-0.5, 0.5]
    float p = 1.3333558e-3f;
    p = fmaf(p, f, 9.6181291e-3f);
    p = fmaf(p, f, 5.5504109e-2f);
    p = fmaf(p, f, 2.4022651e-1f);
    p = fmaf(p, f, 6.9314718e-1f);
    p = fmaf(p, f, 1.0f);
    int e = (int)i;
    return p * __int_as_float((uint32_t)(e + 127) << 23);
}

// ---------------- fp32 -> (bf16 hi, bf16 lo) split ----------------
__global__ __launch_bounds__(256) void split_hl(
    const float* __restrict__ in, __nv_bfloat16* __restrict__ hi,
    __nv_bfloat16* __restrict__ lo, int n4)
{
    int i = blockIdx.x * blockDim.x + threadIdx.x;
    if (i >= n4) return;
    float4 v = ((const float4*)in)[i];
    float f[4] = {v.x, v.y, v.z, v.w};
    unsigned short hs[4], ls[4];
#pragma unroll
    for (int j = 0; j < 4; j++) {
        __nv_bfloat16 hb = __float2bfloat16(f[j]);
        __nv_bfloat16 lb = __float2bfloat16(f[j] - __bfloat162float(hb));
        hs[j] = __bfloat16_as_ushort(hb);
        ls[j] = __bfloat16_as_ushort(lb);
    }
    ((ushort4*)hi)[i] = make_ushort4(hs[0], hs[1], hs[2], hs[3]);
    ((ushort4*)lo)[i] = make_ushort4(ls[0], ls[1], ls[2], ls[3]);
}

// ---------------- bf16x3 NT GEMM via mma.sync, templated epilogue ----------
// MODE 0: fp32 + bias -> C;  MODE 1: fp16*scale -> C16;  MODE 2: bf16 hi/lo.
#define GEMM_SMEM (8 * 16384)

template <int MODE>
__global__ __launch_bounds__(256, 1) void gemm3(
    const __nv_bfloat16* __restrict__ Ah, const __nv_bfloat16* __restrict__ Al,
    const __nv_bfloat16* __restrict__ Bh, const __nv_bfloat16* __restrict__ Bl,
    float* __restrict__ C, __half* __restrict__ C16,
    __nv_bfloat16* __restrict__ Ch, __nv_bfloat16* __restrict__ Cl,
    const float* __restrict__ bias, float scale)
{
    extern __shared__ char smem[];
    const int tid = threadIdx.x, wid = tid >> 5, lane = tid & 31;
    const uint32_t sb = smem_u32(smem);
    const int m0 = blockIdx.y << 7, n0 = blockIdx.x << 7;
    const int warp_m = (wid >> 2) << 6;
    const int warp_n = (wid & 3) << 5;

    const __nv_bfloat16* srcs[4] = {
        Ah + (size_t)m0 * DD, Al + (size_t)m0 * DD,
        Bh + (size_t)n0 * DD, Bl + (size_t)n0 * DD};

    auto tile = [&](int stg, int w) -> uint32_t {
        return sb + (uint32_t)(stg * 4 + w) * 16384;
    };
    auto load_stage = [&](int stg, int kb) {
#pragma unroll
        for (int t = 0; t < 4; t++) {
            const uint32_t tbase = tile(stg, t);
            const __nv_bfloat16* s = srcs[t] + kb * 64;
#pragma unroll
            for (int i = 0; i < 4; i++) {
                int c = tid + (i << 8);
                int r = c >> 3, col = c & 7;
                cp16(tbase + SWZ(r * 128 + col * 16),
                     s + (size_t)r * DD + col * 8);
            }
        }
        asm volatile("cp.async.commit_group;" ::: "memory");
    };

    const int sub = lane >> 3, r8 = lane & 7;
    const int lrow = ((sub & 1) << 3) + r8;
    const int lbyte = (sub >> 1) << 4;

    float acc[4][4][4] = {};
    load_stage(0, 0);

    for (int kb = 0; kb < 16; kb++) {
        const int cur = kb & 1;
        if (kb < 15) load_stage(cur ^ 1, kb + 1);
        if (kb < 15)
            asm volatile("cp.async.wait_group 1;" ::: "memory");
        else
            asm volatile("cp.async.wait_group 0;" ::: "memory");
        __syncthreads();

        const uint32_t AhB = tile(cur, 0), AlB = tile(cur, 1);
        const uint32_t BhB = tile(cur, 2), BlB = tile(cur, 3);

#pragma unroll
        for (int ks = 0; ks < 4; ks++) {
            const int kbyte = (ks << 5) + lbyte;
            uint32_t ah[4][4], al[4][4], bh[2][4], bl[2][4];
#pragma unroll
            for (int mi = 0; mi < 4; mi++) {
                const uint32_t off = SWZ((warp_m + (mi << 4) + lrow) * 128 + kbyte);
                ldm_x4(AhB + off, ah[mi]);
                ldm_x4(AlB + off, al[mi]);
            }
#pragma unroll
            for (int nb = 0; nb < 2; nb++) {
                const uint32_t off = SWZ((warp_n + (nb << 4) + lrow) * 128 + kbyte);
                ldm_x4(BhB + off, bh[nb]);
                ldm_x4(BlB + off, bl[nb]);
            }
#pragma unroll
            for (int mi = 0; mi < 4; mi++)
#pragma unroll
                for (int ni = 0; ni < 4; ni++) {
                    const int nb = ni >> 1, nh = ni & 1;
                    mma_bf16(acc[mi][ni], ah[mi], bh[nb][nh], bh[nb][nh + 2]);
                    mma_bf16(acc[mi][ni], ah[mi], bl[nb][nh], bl[nb][nh + 2]);
                    mma_bf16(acc[mi][ni], al[mi], bh[nb][nh], bh[nb][nh + 2]);
                }
        }
        __syncthreads();
    }

    const int gid = lane >> 2, tig = lane & 3;
#pragma unroll
    for (int mi = 0; mi < 4; mi++)
#pragma unroll
        for (int ni = 0; ni < 4; ni++) {
            const int row = m0 + warp_m + (mi << 4) + gid;
            const int col = n0 + warp_n + (ni << 3) + (tig << 1);
            const float* a = acc[mi][ni];
            if (MODE == 0) {
                float2 bv = *(const float2*)&bias[col];
                *(float2*)&C[(size_t)row * DD + col] =
                    make_float2(a[0] + bv.x, a[1] + bv.y);
                *(float2*)&C[(size_t)(row + 8) * DD + col] =
                    make_float2(a[2] + bv.x, a[3] + bv.y);
            } else if (MODE == 1) {
                *(__half2*)&C16[(size_t)row * DD + col] =
                    __floats2half2_rn(a[0] * scale, a[1] * scale);
                *(__half2*)&C16[(size_t)(row + 8) * DD + col] =
                    __floats2half2_rn(a[2] * scale, a[3] * scale);
            } else {
                uint32_t p0 = packbf(a[0], a[1]);
                float h0 = __uint_as_float(p0 << 16);
                float h1 = __uint_as_float(p0 & 0xffff0000u);
                *(uint32_t*)&Ch[(size_t)row * DD + col] = p0;
                *(uint32_t*)&Cl[(size_t)row * DD + col] =
                    packbf(a[0] - h0, a[1] - h1);
                uint32_t p1 = packbf(a[2], a[3]);
                float h2 = __uint_as_float(p1 << 16);
                float h3 = __uint_as_float(p1 & 0xffff0000u);
                *(uint32_t*)&Ch[(size_t)(row + 8) * DD + col] = p1;
                *(uint32_t*)&Cl[(size_t)(row + 8) * DD + col] =
                    packbf(a[2] - h2, a[3] - h3);
            }
        }
}

// ---------------- flash attention on tensor cores ----------------
// 128 q-rows/CTA, 8 warps (16 rows each, full 128-s width).
// QK^T: fp16 single pass (scale pre-folded into Q). PV: bf16x3.
// Exp via fexp (FMA pipe). O written as bf16 hi/lo in concat layout.
// smem: Q fp16 16KB @0; stage s in {0,1}: K @16K+49152s, Vh @+16K, Vl @+32K.
#define FLASH_SMEM (16384 + 2 * 49152)   // 114688

__global__ __launch_bounds__(256) void flash_mma(
    const __half* __restrict__ Qg, const __half* __restrict__ Kg,
    const __nv_bfloat16* __restrict__ Vhg, const __nv_bfloat16* __restrict__ Vlg,
    __nv_bfloat16* __restrict__ Ohg, __nv_bfloat16* __restrict__ Olg)
{
    extern __shared__ char smem[];
    const uint32_t sb = smem_u32(smem);
    const int tid = threadIdx.x, wid = tid >> 5, lane = tid & 31;
    const int bh = blockIdx.y, b = bh >> 4, h = bh & 15;
    const int t0 = blockIdx.x << 7;
    const int warp_m = wid << 4;
    const int gid = lane >> 2, tig = lane & 3;
    const int sub = lane >> 3, r8 = lane & 7;
    const int lrow = ((sub & 1) << 3) + r8;
    const int lbyte = (sub >> 1) << 4;

    const size_t rb = (size_t)b * TT;

    auto Ks = [&](int s) -> uint32_t { return sb + 16384 + (uint32_t)s * 49152; };
    auto Vh = [&](int s) -> uint32_t { return sb + 32768 + (uint32_t)s * 49152; };
    auto Vl = [&](int s) -> uint32_t { return sb + 49152 + (uint32_t)s * 49152; };

    auto ldtile = [&](uint32_t dst, const void* src_v) {
        const char* src = (const char*)src_v;
#pragma unroll
        for (int i = 0; i < 4; i++) {
            int c = tid + (i << 8);
            int r = c >> 3, k8 = c & 7;
            cp16(dst + SWZ(r * 128 + k8 * 16), src + (size_t)r * DD * 2 + k8 * 16);
        }
    };
    auto load_kv = [&](int stg, int blk) {
        const size_t srow = (rb + (size_t)(blk << 7)) * DD + h * HD;
        ldtile(Ks(stg), Kg + srow);
        ldtile(Vh(stg), Vhg + srow);
        ldtile(Vl(stg), Vlg + srow);
        asm volatile("cp.async.commit_group;" ::: "memory");
    };

    // prologue: Q + KV(0) in group0, KV(1) in group1
    ldtile(sb, Qg + (rb + t0) * DD + h * HD);
    {
        const size_t srow = rb * DD + h * HD;
        ldtile(Ks(0), Kg + srow);
        ldtile(Vh(0), Vhg + srow);
        ldtile(Vl(0), Vlg + srow);
        asm volatile("cp.async.commit_group;" ::: "memory");
    }
    load_kv(1, 1);
    asm volatile("cp.async.wait_group 1;" ::: "memory");
    __syncthreads();

    uint32_t qa[4][4];
#pragma unroll
    for (int ks = 0; ks < 4; ks++)
        ldm_x4(sb + SWZ((warp_m + lrow) * 128 + (ks << 5) + lbyte), qa[ks]);

    float oacc[8][4] = {};
    float mrow[2] = {-1e30f, -1e30f}, lsum[2] = {0.f, 0.f};

    for (int blk = 0; blk < 16; blk++) {
        const int cur = blk & 1;
        float sacc[16][4];
#pragma unroll
        for (int i = 0; i < 16; i++) {
            sacc[i][0] = 0.f; sacc[i][1] = 0.f; sacc[i][2] = 0.f; sacc[i][3] = 0.f;
        }
        // S = Q K^T (fp16)
#pragma unroll
        for (int s8 = 0; s8 < 8; s8++) {
#pragma unroll
            for (int ks = 0; ks < 4; ks++) {
                uint32_t kb[4];
                ldm_x4(Ks(cur) + SWZ(((s8 << 4) + lrow) * 128 + (ks << 5) + lbyte), kb);
                mma_f16(sacc[2 * s8],     qa[ks], kb[0], kb[2]);
                mma_f16(sacc[2 * s8 + 1], qa[ks], kb[1], kb[3]);
            }
        }
        // online softmax (rows gid / gid+8; stats shared over tig quad)
#pragma unroll
        for (int r = 0; r < 2; r++) {
            float mx = sacc[0][2 * r];
#pragma unroll
            for (int ni = 0; ni < 16; ni++)
                mx = fmaxf(mx, fmaxf(sacc[ni][2 * r], sacc[ni][2 * r + 1]));
            mx = fmaxf(mx, __shfl_xor_sync(0xffffffffu, mx, 1));
            mx = fmaxf(mx, __shfl_xor_sync(0xffffffffu, mx, 2));
            const float mn = fmaxf(mrow[r], mx);
            const float al = fexp(mrow[r] - mn);
            mrow[r] = mn;
            float rs = 0.f;
#pragma unroll
            for (int ni = 0; ni < 16; ni++) {
                float p0 = fexp(sacc[ni][2 * r] - mn);
                float p1 = fexp(sacc[ni][2 * r + 1] - mn);
                sacc[ni][2 * r] = p0; sacc[ni][2 * r + 1] = p1;
                rs += p0 + p1;
            }
            rs += __shfl_xor_sync(0xffffffffu, rs, 1);
            rs += __shfl_xor_sync(0xffffffffu, rs, 2);
            lsum[r] = lsum[r] * al + rs;
#pragma unroll
            for (int nj = 0; nj < 8; nj++) {
                oacc[nj][2 * r] *= al; oacc[nj][2 * r + 1] *= al;
            }
        }
        // O += P V (bf16x3: Ph*Vh + Ph*Vl + Pl*Vh)
#pragma unroll
        for (int ks = 0; ks < 8; ks++) {
            uint32_t pah[4], pal[4];
#pragma unroll
            for (int q = 0; q < 2; q++) {
                const float* c = sacc[2 * ks + q];
                uint32_t h01 = packbf(c[0], c[1]);
                float f0 = __uint_as_float(h01 << 16);
                float f1 = __uint_as_float(h01 & 0xffff0000u);
                uint32_t h23 = packbf(c[2], c[3]);
                float f2 = __uint_as_float(h23 << 16);
                float f3 = __uint_as_float(h23 & 0xffff0000u);
                pah[2 * q] = h01; pah[2 * q + 1] = h23;
                pal[2 * q] = packbf(c[0] - f0, c[1] - f1);
                pal[2 * q + 1] = packbf(c[2] - f2, c[3] - f3);
            }
#pragma unroll
            for (int hq = 0; hq < 4; hq++) {
                const uint32_t off = SWZ(((ks << 4) + lrow) * 128 + (hq << 5) + lbyte);
                uint32_t vh4[4], vl4[4];
                ldm_x4t(Vh(cur) + off, vh4);
                ldm_x4t(Vl(cur) + off, vl4);
                mma_bf16(oacc[2 * hq],     pah, vh4[0], vh4[1]);
                mma_bf16(oacc[2 * hq + 1], pah, vh4[2], vh4[3]);
                mma_bf16(oacc[2 * hq],     pah, vl4[0], vl4[1]);
                mma_bf16(oacc[2 * hq + 1], pah, vl4[2], vl4[3]);
                mma_bf16(oacc[2 * hq],     pal, vh4[0], vh4[1]);
                mma_bf16(oacc[2 * hq + 1], pal, vh4[2], vh4[3]);
            }
        }
        __syncthreads();
        if (blk + 2 < 16) load_kv(cur, blk + 2);
        if (blk + 1 < 16) {
            if (blk + 2 < 16)
                asm volatile("cp.async.wait_group 1;" ::: "memory");
            else
                asm volatile("cp.async.wait_group 0;" ::: "memory");
            __syncthreads();
        }
    }

    // epilogue: normalize, bf16 hi/lo, concat layout
    const float inv0 = 1.f / lsum[0], inv1 = 1.f / lsum[1];
#pragma unroll
    for (int nj = 0; nj < 8; nj++) {
        const int col = h * HD + (nj << 3) + (tig << 1);
        const size_t r0 = (rb + t0 + warp_m + gid) * DD + col;
        const size_t r1 = r0 + (size_t)8 * DD;
        float a0 = oacc[nj][0] * inv0, a1 = oacc[nj][1] * inv0;
        float a2 = oacc[nj][2] * inv1, a3 = oacc[nj][3] * inv1;
        uint32_t p0 = packbf(a0, a1);
        float h0 = __uint_as_float(p0 << 16), h1 = __uint_as_float(p0 & 0xffff0000u);
        *(uint32_t*)&Ohg[r0] = p0;
        *(uint32_t*)&Olg[r0] = packbf(a0 - h0, a1 - h1);
        uint32_t p1 = packbf(a2, a3);
        float h2 = __uint_as_float(p1 << 16), h3 = __uint_as_float(p1 & 0xffff0000u);
        *(uint32_t*)&Ohg[r1] = p1;
        *(uint32_t*)&Olg[r1] = packbf(a2 - h2, a3 - h3);
    }
}

// ---------------- launcher ----------------
extern "C" void kernel_launch(void* const* d_in, const int* in_sizes, int n_in,
                              void* d_out, int out_size)
{
    const float* x  = (const float*)d_in[0];
    const float* Wq = (const float*)d_in[1];
    const float* Wk = (const float*)d_in[2];
    const float* Wv = (const float*)d_in[3];
    const float* Wo = (const float*)d_in[4];
    const float* bo = (const float*)d_in[5];
    float* out = (float*)d_out;

    __nv_bfloat16 *xh, *xl, *wh, *wl, *vh, *vl, *oh, *ol;
    __half *q16, *k16;
    cudaGetSymbolAddress((void**)&xh, g_xh);
    cudaGetSymbolAddress((void**)&xl, g_xl);
    cudaGetSymbolAddress((void**)&wh, g_wh);
    cudaGetSymbolAddress((void**)&wl, g_wl);
    cudaGetSymbolAddress((void**)&vh, g_vh);
    cudaGetSymbolAddress((void**)&vl, g_vl);
    cudaGetSymbolAddress((void**)&oh, g_oh);
    cudaGetSymbolAddress((void**)&ol, g_ol);
    cudaGetSymbolAddress((void**)&q16, g_q16);
    cudaGetSymbolAddress((void**)&k16, g_k16);

    cudaFuncSetAttribute(gemm3<0>, cudaFuncAttributeMaxDynamicSharedMemorySize, GEMM_SMEM);
    cudaFuncSetAttribute(gemm3<1>, cudaFuncAttributeMaxDynamicSharedMemorySize, GEMM_SMEM);
    cudaFuncSetAttribute(gemm3<2>, cudaFuncAttributeMaxDynamicSharedMemorySize, GEMM_SMEM);
    cudaFuncSetAttribute(flash_mma, cudaFuncAttributeMaxDynamicSharedMemorySize, FLASH_SMEM);

    const int n4x = MROWS * DD / 4;
    const int n4w = DD * DD / 4;
    split_hl<<<n4x / 256, 256>>>(x, xh, xl, n4x);
    const float* Ws[4] = {Wq, Wk, Wv, Wo};
    for (int i = 0; i < 4; i++)
        split_hl<<<n4w / 256, 256>>>(Ws[i], wh + (size_t)i * DD * DD,
                                     wl + (size_t)i * DD * DD, n4w);

    dim3 gg(DD / 128, MROWS / 128);  // (8, 64)
    // Q (scale folded), K as fp16
    gemm3<1><<<gg, 256, GEMM_SMEM>>>(xh, xl, wh, wl,
                                     nullptr, q16, nullptr, nullptr, nullptr, 0.125f);
    gemm3<1><<<gg, 256, GEMM_SMEM>>>(xh, xl, wh + (size_t)DD * DD, wl + (size_t)DD * DD,
                                     nullptr, k16, nullptr, nullptr, nullptr, 1.0f);
    // V as bf16 hi/lo
    gemm3<2><<<gg, 256, GEMM_SMEM>>>(xh, xl, wh + 2 * (size_t)DD * DD, wl + 2 * (size_t)DD * DD,
                                     nullptr, nullptr, vh, vl, nullptr, 1.0f);

    flash_mma<<<dim3(TT / 128, BB * HH), 256, FLASH_SMEM>>>(q16, k16, vh, vl, oh, ol);

    // output projection + bias
    gemm3<0><<<gg, 256, GEMM_SMEM>>>(oh, ol, wh + 3 * (size_t)DD * DD, wl + 3 * (size_t)DD * DD,
                                     out, nullptr, nullptr, nullptr, bo, 1.0f);
}

// round 9
// speedup vs baseline: 7.2971x; 1.9905x over previous
#include <cuda_runtime.h>
#include <cuda_bf16.h>
#include <cuda_fp16.h>
#include <cstdint>

#define BB 4
#define TT 2048
#define DD 1024
#define HH 16
#define HD 64
#define MROWS (BB * TT)   // 8192

// ---------------- scratch (alloc-free rule: device globals) ----------------
__device__ __half g_x16[MROWS * DD];
__device__ __half g_w16[4][DD * DD];
__device__ __half g_q16[MROWS * DD], g_k16[MROWS * DD], g_v16[MROWS * DD];
__device__ __half g_o16[MROWS * DD];

// ---------------- helpers ----------------
__device__ __forceinline__ uint32_t smem_u32(const void* p) {
    uint32_t a;
    asm("{ .reg .u64 t; cvta.to.shared.u64 t, %1; cvt.u32.u64 %0, t; }"
        : "=r"(a) : "l"(p));
    return a;
}
#define SWZ(o) ((o) ^ (((o) >> 3) & 0x70))

__device__ __forceinline__ void cp16(uint32_t d, const void* s) {
    asm volatile("cp.async.cg.shared.global [%0], [%1], 16;"
                 :: "r"(d), "l"(s));
}
__device__ __forceinline__ void ldm_x4(uint32_t a, uint32_t* r) {
    asm volatile("ldmatrix.sync.aligned.m8n8.x4.shared.b16 {%0,%1,%2,%3}, [%4];"
                 : "=r"(r[0]), "=r"(r[1]), "=r"(r[2]), "=r"(r[3]) : "r"(a));
}
__device__ __forceinline__ void ldm_x4t(uint32_t a, uint32_t* r) {
    asm volatile("ldmatrix.sync.aligned.m8n8.x4.trans.shared.b16 {%0,%1,%2,%3}, [%4];"
                 : "=r"(r[0]), "=r"(r[1]), "=r"(r[2]), "=r"(r[3]) : "r"(a));
}
__device__ __forceinline__ void mma_f16(float* d, const uint32_t* a,
                                        uint32_t b0, uint32_t b1) {
    asm volatile(
        "mma.sync.aligned.m16n8k16.row.col.f32.f16.f16.f32 "
        "{%0,%1,%2,%3},{%4,%5,%6,%7},{%8,%9},{%0,%1,%2,%3};"
        : "+f"(d[0]), "+f"(d[1]), "+f"(d[2]), "+f"(d[3])
        : "r"(a[0]), "r"(a[1]), "r"(a[2]), "r"(a[3]), "r"(b0), "r"(b1));
}
// pack two fp32 into one f16x2 register (lo -> low half, hi -> high half)
__device__ __forceinline__ uint32_t packh2(float lo, float hi) {
    uint32_t r;
    asm("cvt.rn.f16x2.f32 %0, %1, %2;" : "=r"(r) : "f"(hi), "f"(lo));
    return r;
}
// fast exp on FMA/ALU pipes (avoids MUFU); ~2e-6 rel for x <= 0
__device__ __forceinline__ float fexp(float x) {
    const float l2e = 1.4426950408889634f;
    x = fmaxf(x, -87.0f);
    float t = fmaf(x, l2e, 12582912.0f);
    float i = t - 12582912.0f;
    float f = fmaf(x, l2e, -i);
    float p = 1.3333558e-3f;
    p = fmaf(p, f, 9.6181291e-3f);
    p = fmaf(p, f, 5.5504109e-2f);
    p = fmaf(p, f, 2.4022651e-1f);
    p = fmaf(p, f, 6.9314718e-1f);
    p = fmaf(p, f, 1.0f);
    int e = (int)i;
    return p * __int_as_float((uint32_t)(e + 127) << 23);
}

// ---------------- fp32 -> fp16 convert ----------------
__global__ __launch_bounds__(256) void cvt16(
    const float* __restrict__ in, __half* __restrict__ out, int n4)
{
    int i = blockIdx.x * blockDim.x + threadIdx.x;
    if (i >= n4) return;
    float4 v = ((const float4*)in)[i];
    uint32_t* o = (uint32_t*)out;
    o[2 * i]     = packh2(v.x, v.y);
    o[2 * i + 1] = packh2(v.z, v.w);
}

// ---------------- single-pass fp16 NT GEMM via mma.sync ----------------
// C[M,1024] = A16 * B16^T; MODE 0: fp32 + bias -> C; MODE 1: fp16*scale -> C16.
// 128x128 CTA tile, 8 warps (2m x 4n), K blocks of 64, 2-stage cp.async.
// smem: (stage*2 + which)*16KB; which: 0=A 1=B. 64KB total -> 2 CTAs/SM.
#define GEMM_SMEM (4 * 16384)

template <int MODE>
__global__ __launch_bounds__(256, 2) void gemm16(
    const __half* __restrict__ A, const __half* __restrict__ B,
    float* __restrict__ C, __half* __restrict__ C16,
    const float* __restrict__ bias, float scale)
{
    extern __shared__ char smem[];
    const int tid = threadIdx.x, wid = tid >> 5, lane = tid & 31;
    const uint32_t sb = smem_u32(smem);
    const int m0 = blockIdx.y << 7, n0 = blockIdx.x << 7;
    const int warp_m = (wid >> 2) << 6;
    const int warp_n = (wid & 3) << 5;

    const __half* srcs[2] = {A + (size_t)m0 * DD, B + (size_t)n0 * DD};

    auto tile = [&](int stg, int w) -> uint32_t {
        return sb + (uint32_t)(stg * 2 + w) * 16384;
    };
    auto load_stage = [&](int stg, int kb) {
#pragma unroll
        for (int t = 0; t < 2; t++) {
            const uint32_t tbase = tile(stg, t);
            const __half* s = srcs[t] + kb * 64;
#pragma unroll
            for (int i = 0; i < 4; i++) {
                int c = tid + (i << 8);
                int r = c >> 3, col = c & 7;
                cp16(tbase + SWZ(r * 128 + col * 16),
                     s + (size_t)r * DD + col * 8);
            }
        }
        asm volatile("cp.async.commit_group;" ::: "memory");
    };

    const int sub = lane >> 3, r8 = lane & 7;
    const int lrow = ((sub & 1) << 3) + r8;
    const int lbyte = (sub >> 1) << 4;

    float acc[4][4][4] = {};
    load_stage(0, 0);

    for (int kb = 0; kb < 16; kb++) {
        const int cur = kb & 1;
        if (kb < 15) load_stage(cur ^ 1, kb + 1);
        if (kb < 15)
            asm volatile("cp.async.wait_group 1;" ::: "memory");
        else
            asm volatile("cp.async.wait_group 0;" ::: "memory");
        __syncthreads();

        const uint32_t AB = tile(cur, 0), BBs = tile(cur, 1);

#pragma unroll
        for (int ks = 0; ks < 4; ks++) {
            const int kbyte = (ks << 5) + lbyte;
            uint32_t af[4][4], bf[2][4];
#pragma unroll
            for (int mi = 0; mi < 4; mi++)
                ldm_x4(AB + SWZ((warp_m + (mi << 4) + lrow) * 128 + kbyte), af[mi]);
#pragma unroll
            for (int nb = 0; nb < 2; nb++)
                ldm_x4(BBs + SWZ((warp_n + (nb << 4) + lrow) * 128 + kbyte), bf[nb]);
#pragma unroll
            for (int mi = 0; mi < 4; mi++)
#pragma unroll
                for (int ni = 0; ni < 4; ni++) {
                    const int nb = ni >> 1, nh = ni & 1;
                    mma_f16(acc[mi][ni], af[mi], bf[nb][nh], bf[nb][nh + 2]);
                }
        }
        __syncthreads();
    }

    const int gid = lane >> 2, tig = lane & 3;
#pragma unroll
    for (int mi = 0; mi < 4; mi++)
#pragma unroll
        for (int ni = 0; ni < 4; ni++) {
            const int row = m0 + warp_m + (mi << 4) + gid;
            const int col = n0 + warp_n + (ni << 3) + (tig << 1);
            const float* a = acc[mi][ni];
            if (MODE == 0) {
                float2 bv = *(const float2*)&bias[col];
                *(float2*)&C[(size_t)row * DD + col] =
                    make_float2(a[0] + bv.x, a[1] + bv.y);
                *(float2*)&C[(size_t)(row + 8) * DD + col] =
                    make_float2(a[2] + bv.x, a[3] + bv.y);
            } else {
                *(uint32_t*)&C16[(size_t)row * DD + col] =
                    packh2(a[0] * scale, a[1] * scale);
                *(uint32_t*)&C16[(size_t)(row + 8) * DD + col] =
                    packh2(a[2] * scale, a[3] * scale);
            }
        }
}

// ---------------- flash attention, all fp16 MMA ----------------
// 128 q-rows/CTA, 8 warps. QK^T fp16 (scale folded in Q), PV fp16 single-pass.
// smem: Q 16KB @0; stage s: K @16K+32768s, V @+16K. Total 80KB.
#define FLASH_SMEM (16384 + 2 * 32768)   // 81920

__global__ __launch_bounds__(256) void flash_mma(
    const __half* __restrict__ Qg, const __half* __restrict__ Kg,
    const __half* __restrict__ Vg, __half* __restrict__ Og)
{
    extern __shared__ char smem[];
    const uint32_t sb = smem_u32(smem);
    const int tid = threadIdx.x, wid = tid >> 5, lane = tid & 31;
    const int bh = blockIdx.y, b = bh >> 4, h = bh & 15;
    const int t0 = blockIdx.x << 7;
    const int warp_m = wid << 4;
    const int gid = lane >> 2, tig = lane & 3;
    const int sub = lane >> 3, r8 = lane & 7;
    const int lrow = ((sub & 1) << 3) + r8;
    const int lbyte = (sub >> 1) << 4;

    const size_t rb = (size_t)b * TT;

    auto Ks = [&](int s) -> uint32_t { return sb + 16384 + (uint32_t)s * 32768; };
    auto Vs = [&](int s) -> uint32_t { return sb + 32768 + (uint32_t)s * 32768; };

    auto ldtile = [&](uint32_t dst, const void* src_v) {
        const char* src = (const char*)src_v;
#pragma unroll
        for (int i = 0; i < 4; i++) {
            int c = tid + (i << 8);
            int r = c >> 3, k8 = c & 7;
            cp16(dst + SWZ(r * 128 + k8 * 16), src + (size_t)r * DD * 2 + k8 * 16);
        }
    };
    auto load_kv = [&](int stg, int blk) {
        const size_t srow = (rb + (size_t)(blk << 7)) * DD + h * HD;
        ldtile(Ks(stg), Kg + srow);
        ldtile(Vs(stg), Vg + srow);
        asm volatile("cp.async.commit_group;" ::: "memory");
    };

    ldtile(sb, Qg + (rb + t0) * DD + h * HD);
    load_kv(0, 0);
    load_kv(1, 1);
    asm volatile("cp.async.wait_group 1;" ::: "memory");
    __syncthreads();

    uint32_t qa[4][4];
#pragma unroll
    for (int ks = 0; ks < 4; ks++)
        ldm_x4(sb + SWZ((warp_m + lrow) * 128 + (ks << 5) + lbyte), qa[ks]);

    float oacc[8][4] = {};
    float mrow[2] = {-1e30f, -1e30f}, lsum[2] = {0.f, 0.f};

    for (int blk = 0; blk < 16; blk++) {
        const int cur = blk & 1;
        float sacc[16][4];
#pragma unroll
        for (int i = 0; i < 16; i++) {
            sacc[i][0] = 0.f; sacc[i][1] = 0.f; sacc[i][2] = 0.f; sacc[i][3] = 0.f;
        }
        // S = Q K^T
#pragma unroll
        for (int s8 = 0; s8 < 8; s8++) {
#pragma unroll
            for (int ks = 0; ks < 4; ks++) {
                uint32_t kf[4];
                ldm_x4(Ks(cur) + SWZ(((s8 << 4) + lrow) * 128 + (ks << 5) + lbyte), kf);
                mma_f16(sacc[2 * s8],     qa[ks], kf[0], kf[2]);
                mma_f16(sacc[2 * s8 + 1], qa[ks], kf[1], kf[3]);
            }
        }
        // online softmax
#pragma unroll
        for (int r = 0; r < 2; r++) {
            float mx = sacc[0][2 * r];
#pragma unroll
            for (int ni = 0; ni < 16; ni++)
                mx = fmaxf(mx, fmaxf(sacc[ni][2 * r], sacc[ni][2 * r + 1]));
            mx = fmaxf(mx, __shfl_xor_sync(0xffffffffu, mx, 1));
            mx = fmaxf(mx, __shfl_xor_sync(0xffffffffu, mx, 2));
            const float mn = fmaxf(mrow[r], mx);
            const float al = fexp(mrow[r] - mn);
            mrow[r] = mn;
            float rs = 0.f;
#pragma unroll
            for (int ni = 0; ni < 16; ni++) {
                float p0 = fexp(sacc[ni][2 * r] - mn);
                float p1 = fexp(sacc[ni][2 * r + 1] - mn);
                sacc[ni][2 * r] = p0; sacc[ni][2 * r + 1] = p1;
                rs += p0 + p1;
            }
            rs += __shfl_xor_sync(0xffffffffu, rs, 1);
            rs += __shfl_xor_sync(0xffffffffu, rs, 2);
            lsum[r] = lsum[r] * al + rs;
#pragma unroll
            for (int nj = 0; nj < 8; nj++) {
                oacc[nj][2 * r] *= al; oacc[nj][2 * r + 1] *= al;
            }
        }
        // O += P V (single-pass fp16)
#pragma unroll
        for (int ks = 0; ks < 8; ks++) {
            uint32_t pa[4];
#pragma unroll
            for (int q = 0; q < 2; q++) {
                const float* c = sacc[2 * ks + q];
                pa[2 * q]     = packh2(c[0], c[1]);
                pa[2 * q + 1] = packh2(c[2], c[3]);
            }
#pragma unroll
            for (int hq = 0; hq < 4; hq++) {
                uint32_t v4[4];
                ldm_x4t(Vs(cur) + SWZ(((ks << 4) + lrow) * 128 + (hq << 5) + lbyte), v4);
                mma_f16(oacc[2 * hq],     pa, v4[0], v4[1]);
                mma_f16(oacc[2 * hq + 1], pa, v4[2], v4[3]);
            }
        }
        __syncthreads();
        if (blk + 2 < 16) load_kv(cur, blk + 2);
        if (blk + 1 < 16) {
            if (blk + 2 < 16)
                asm volatile("cp.async.wait_group 1;" ::: "memory");
            else
                asm volatile("cp.async.wait_group 0;" ::: "memory");
            __syncthreads();
        }
    }

    // epilogue: normalize, fp16 out, concat layout
    const float inv0 = 1.f / lsum[0], inv1 = 1.f / lsum[1];
#pragma unroll
    for (int nj = 0; nj < 8; nj++) {
        const int col = h * HD + (nj << 3) + (tig << 1);
        const size_t r0 = (rb + t0 + warp_m + gid) * DD + col;
        const size_t r1 = r0 + (size_t)8 * DD;
        *(uint32_t*)&Og[r0] = packh2(oacc[nj][0] * inv0, oacc[nj][1] * inv0);
        *(uint32_t*)&Og[r1] = packh2(oacc[nj][2] * inv1, oacc[nj][3] * inv1);
    }
}

// ---------------- launcher ----------------
extern "C" void kernel_launch(void* const* d_in, const int* in_sizes, int n_in,
                              void* d_out, int out_size)
{
    const float* x  = (const float*)d_in[0];
    const float* Wq = (const float*)d_in[1];
    const float* Wk = (const float*)d_in[2];
    const float* Wv = (const float*)d_in[3];
    const float* Wo = (const float*)d_in[4];
    const float* bo = (const float*)d_in[5];
    float* out = (float*)d_out;

    __half *x16, *w16, *q16, *k16, *v16, *o16;
    cudaGetSymbolAddress((void**)&x16, g_x16);
    cudaGetSymbolAddress((void**)&w16, g_w16);
    cudaGetSymbolAddress((void**)&q16, g_q16);
    cudaGetSymbolAddress((void**)&k16, g_k16);
    cudaGetSymbolAddress((void**)&v16, g_v16);
    cudaGetSymbolAddress((void**)&o16, g_o16);

    cudaFuncSetAttribute(gemm16<0>, cudaFuncAttributeMaxDynamicSharedMemorySize, GEMM_SMEM);
    cudaFuncSetAttribute(gemm16<1>, cudaFuncAttributeMaxDynamicSharedMemorySize, GEMM_SMEM);
    cudaFuncSetAttribute(flash_mma, cudaFuncAttributeMaxDynamicSharedMemorySize, FLASH_SMEM);

    const int n4x = MROWS * DD / 4;
    const int n4w = DD * DD / 4;
    cvt16<<<n4x / 256, 256>>>(x, x16, n4x);
    const float* Ws[4] = {Wq, Wk, Wv, Wo};
    for (int i = 0; i < 4; i++)
        cvt16<<<n4w / 256, 256>>>(Ws[i], w16 + (size_t)i * DD * DD, n4w);

    dim3 gg(DD / 128, MROWS / 128);  // (8, 64)
    gemm16<1><<<gg, 256, GEMM_SMEM>>>(x16, w16,                       nullptr, q16, nullptr, 0.125f);
    gemm16<1><<<gg, 256, GEMM_SMEM>>>(x16, w16 + (size_t)DD * DD,     nullptr, k16, nullptr, 1.0f);
    gemm16<1><<<gg, 256, GEMM_SMEM>>>(x16, w16 + 2 * (size_t)DD * DD, nullptr, v16, nullptr, 1.0f);

    flash_mma<<<dim3(TT / 128, BB * HH), 256, FLASH_SMEM>>>(q16, k16, v16, o16);

    gemm16<0><<<gg, 256, GEMM_SMEM>>>(o16, w16 + 3 * (size_t)DD * DD, out, nullptr, bo, 1.0f);
}

// round 10
// speedup vs baseline: 7.4102x; 1.0155x over previous
#include <cuda_runtime.h>
#include <cuda_bf16.h>
#include <cuda_fp16.h>
#include <cstdint>

#define BB 4
#define TT 2048
#define DD 1024
#define HH 16
#define HD 64
#define MROWS (BB * TT)   // 8192

// ---------------- scratch (alloc-free rule: device globals) ----------------
__device__ __half g_x16[MROWS * DD];
__device__ __half g_w16[4][DD * DD];
__device__ __half g_q16[MROWS * DD], g_k16[MROWS * DD], g_v16[MROWS * DD];
__device__ __half g_o16[MROWS * DD];

// ---------------- helpers ----------------
__device__ __forceinline__ uint32_t smem_u32(const void* p) {
    uint32_t a;
    asm("{ .reg .u64 t; cvta.to.shared.u64 t, %1; cvt.u32.u64 %0, t; }"
        : "=r"(a) : "l"(p));
    return a;
}
#define SWZ(o) ((o) ^ (((o) >> 3) & 0x70))

__device__ __forceinline__ void cp16(uint32_t d, const void* s) {
    asm volatile("cp.async.cg.shared.global [%0], [%1], 16;"
                 :: "r"(d), "l"(s));
}
__device__ __forceinline__ void ldm_x4(uint32_t a, uint32_t* r) {
    asm volatile("ldmatrix.sync.aligned.m8n8.x4.shared.b16 {%0,%1,%2,%3}, [%4];"
                 : "=r"(r[0]), "=r"(r[1]), "=r"(r[2]), "=r"(r[3]) : "r"(a));
}
__device__ __forceinline__ void ldm_x4t(uint32_t a, uint32_t* r) {
    asm volatile("ldmatrix.sync.aligned.m8n8.x4.trans.shared.b16 {%0,%1,%2,%3}, [%4];"
                 : "=r"(r[0]), "=r"(r[1]), "=r"(r[2]), "=r"(r[3]) : "r"(a));
}
__device__ __forceinline__ void mma_f16(float* d, const uint32_t* a,
                                        uint32_t b0, uint32_t b1) {
    asm volatile(
        "mma.sync.aligned.m16n8k16.row.col.f32.f16.f16.f32 "
        "{%0,%1,%2,%3},{%4,%5,%6,%7},{%8,%9},{%0,%1,%2,%3};"
        : "+f"(d[0]), "+f"(d[1]), "+f"(d[2]), "+f"(d[3])
        : "r"(a[0]), "r"(a[1]), "r"(a[2]), "r"(a[3]), "r"(b0), "r"(b1));
}
// pack two fp32 into one f16x2 register (lo -> low half, hi -> high half)
__device__ __forceinline__ uint32_t packh2(float lo, float hi) {
    uint32_t r;
    asm("cvt.rn.f16x2.f32 %0, %1, %2;" : "=r"(r) : "f"(hi), "f"(lo));
    return r;
}
// fast exp on FMA/ALU pipes (avoids MUFU); ~2e-6 rel for x <= 0
__device__ __forceinline__ float fexp(float x) {
    const float l2e = 1.4426950408889634f;
    x = fmaxf(x, -87.0f);
    float t = fmaf(x, l2e, 12582912.0f);
    float i = t - 12582912.0f;
    float f = fmaf(x, l2e, -i);
    float p = 1.3333558e-3f;
    p = fmaf(p, f, 9.6181291e-3f);
    p = fmaf(p, f, 5.5504109e-2f);
    p = fmaf(p, f, 2.4022651e-1f);
    p = fmaf(p, f, 6.9314718e-1f);
    p = fmaf(p, f, 1.0f);
    int e = (int)i;
    return p * __int_as_float((uint32_t)(e + 127) << 23);
}

// ---------------- fp32 -> fp16 converts ----------------
__global__ __launch_bounds__(256) void cvt16(
    const float* __restrict__ in, __half* __restrict__ out, int n4)
{
    int i = blockIdx.x * blockDim.x + threadIdx.x;
    if (i >= n4) return;
    float4 v = ((const float4*)in)[i];
    uint32_t* o = (uint32_t*)out;
    o[2 * i]     = packh2(v.x, v.y);
    o[2 * i + 1] = packh2(v.z, v.w);
}
// all four weights in one launch; blockIdx.y selects the matrix
__global__ __launch_bounds__(256) void cvt16w(
    const float* __restrict__ w0, const float* __restrict__ w1,
    const float* __restrict__ w2, const float* __restrict__ w3,
    __half* __restrict__ out)
{
    const float* srcs[4] = {w0, w1, w2, w3};
    const int m = blockIdx.y;
    const int i = blockIdx.x * blockDim.x + threadIdx.x;   // < DD*DD/4
    float4 v = ((const float4*)srcs[m])[i];
    uint32_t* o = (uint32_t*)(out + (size_t)m * DD * DD);
    o[2 * i]     = packh2(v.x, v.y);
    o[2 * i + 1] = packh2(v.z, v.w);
}

// ---------------- single-pass fp16 NT GEMM via mma.sync ----------------
// C[M,1024] = A16 * B16^T; MODE 0: fp32 + bias -> C; MODE 1: fp16*scale -> C16.
// 128x128 CTA tile, 8 warps (2m x 4n), K blocks of 64, 3-stage cp.async
// pipeline with ONE __syncthreads per K-block.
// smem: (stage*2 + which)*16KB; which: 0=A 1=B. 96KB total -> 2 CTAs/SM.
#define GEMM_SMEM (6 * 16384)

template <int MODE>
__global__ __launch_bounds__(256, 2) void gemm16(
    const __half* __restrict__ A, const __half* __restrict__ B,
    float* __restrict__ C, __half* __restrict__ C16,
    const float* __restrict__ bias, float scale)
{
    extern __shared__ char smem[];
    const int tid = threadIdx.x, wid = tid >> 5, lane = tid & 31;
    const uint32_t sb = smem_u32(smem);
    const int m0 = blockIdx.y << 7, n0 = blockIdx.x << 7;
    const int warp_m = (wid >> 2) << 6;
    const int warp_n = (wid & 3) << 5;

    const __half* srcs[2] = {A + (size_t)m0 * DD, B + (size_t)n0 * DD};

    auto tile = [&](int stg, int w) -> uint32_t {
        return sb + (uint32_t)(stg * 2 + w) * 16384;
    };
    auto load_stage = [&](int stg, int kb) {
#pragma unroll
        for (int t = 0; t < 2; t++) {
            const uint32_t tbase = tile(stg, t);
            const __half* s = srcs[t] + kb * 64;
#pragma unroll
            for (int i = 0; i < 4; i++) {
                int c = tid + (i << 8);
                int r = c >> 3, col = c & 7;
                cp16(tbase + SWZ(r * 128 + col * 16),
                     s + (size_t)r * DD + col * 8);
            }
        }
        asm volatile("cp.async.commit_group;" ::: "memory");
    };

    const int sub = lane >> 3, r8 = lane & 7;
    const int lrow = ((sub & 1) << 3) + r8;
    const int lbyte = (sub >> 1) << 4;

    float acc[4][4][4] = {};
    load_stage(0, 0);
    load_stage(1, 1);

    for (int kb = 0; kb < 16; kb++) {
        const int cur = kb % 3;
        if (kb + 1 < 16)
            asm volatile("cp.async.wait_group 1;" ::: "memory");
        else
            asm volatile("cp.async.wait_group 0;" ::: "memory");
        __syncthreads();   // single sync: cur's data visible; (kb+2)%3's last
                           // readers finished before the previous sync

        if (kb + 2 < 16) load_stage((kb + 2) % 3, kb + 2);

        const uint32_t AB = tile(cur, 0), BBs = tile(cur, 1);
#pragma unroll
        for (int ks = 0; ks < 4; ks++) {
            const int kbyte = (ks << 5) + lbyte;
            uint32_t af[4][4], bf[2][4];
#pragma unroll
            for (int mi = 0; mi < 4; mi++)
                ldm_x4(AB + SWZ((warp_m + (mi << 4) + lrow) * 128 + kbyte), af[mi]);
#pragma unroll
            for (int nb = 0; nb < 2; nb++)
                ldm_x4(BBs + SWZ((warp_n + (nb << 4) + lrow) * 128 + kbyte), bf[nb]);
#pragma unroll
            for (int mi = 0; mi < 4; mi++)
#pragma unroll
                for (int ni = 0; ni < 4; ni++) {
                    const int nb = ni >> 1, nh = ni & 1;
                    mma_f16(acc[mi][ni], af[mi], bf[nb][nh], bf[nb][nh + 2]);
                }
        }
    }

    const int gid = lane >> 2, tig = lane & 3;
#pragma unroll
    for (int mi = 0; mi < 4; mi++)
#pragma unroll
        for (int ni = 0; ni < 4; ni++) {
            const int row = m0 + warp_m + (mi << 4) + gid;
            const int col = n0 + warp_n + (ni << 3) + (tig << 1);
            const float* a = acc[mi][ni];
            if (MODE == 0) {
                float2 bv = *(const float2*)&bias[col];
                *(float2*)&C[(size_t)row * DD + col] =
                    make_float2(a[0] + bv.x, a[1] + bv.y);
                *(float2*)&C[(size_t)(row + 8) * DD + col] =
                    make_float2(a[2] + bv.x, a[3] + bv.y);
            } else {
                *(uint32_t*)&C16[(size_t)row * DD + col] =
                    packh2(a[0] * scale, a[1] * scale);
                *(uint32_t*)&C16[(size_t)(row + 8) * DD + col] =
                    packh2(a[2] * scale, a[3] * scale);
            }
        }
}

// ---------------- flash attention, all fp16 MMA ----------------
// 128 q-rows/CTA, 8 warps. QK^T fp16 (scale folded in Q), PV fp16.
// 3-stage KV pipeline, one __syncthreads per s-block.
// smem: Q 16KB @0; stage s in {0,1,2}: K @16K+32768s, V @+16K. Total 112KB.
#define FLASH_SMEM (16384 + 3 * 32768)   // 114688

__global__ __launch_bounds__(256) void flash_mma(
    const __half* __restrict__ Qg, const __half* __restrict__ Kg,
    const __half* __restrict__ Vg, __half* __restrict__ Og)
{
    extern __shared__ char smem[];
    const uint32_t sb = smem_u32(smem);
    const int tid = threadIdx.x, wid = tid >> 5, lane = tid & 31;
    const int bh = blockIdx.y, b = bh >> 4, h = bh & 15;
    const int t0 = blockIdx.x << 7;
    const int warp_m = wid << 4;
    const int gid = lane >> 2, tig = lane & 3;
    const int sub = lane >> 3, r8 = lane & 7;
    const int lrow = ((sub & 1) << 3) + r8;
    const int lbyte = (sub >> 1) << 4;

    const size_t rb = (size_t)b * TT;

    auto Ks = [&](int s) -> uint32_t { return sb + 16384 + (uint32_t)s * 32768; };
    auto Vs = [&](int s) -> uint32_t { return sb + 32768 + (uint32_t)s * 32768; };

    auto ldtile = [&](uint32_t dst, const void* src_v) {
        const char* src = (const char*)src_v;
#pragma unroll
        for (int i = 0; i < 4; i++) {
            int c = tid + (i << 8);
            int r = c >> 3, k8 = c & 7;
            cp16(dst + SWZ(r * 128 + k8 * 16), src + (size_t)r * DD * 2 + k8 * 16);
        }
    };
    auto load_kv = [&](int stg, int blk) {
        const size_t srow = (rb + (size_t)(blk << 7)) * DD + h * HD;
        ldtile(Ks(stg), Kg + srow);
        ldtile(Vs(stg), Vg + srow);
        asm volatile("cp.async.commit_group;" ::: "memory");
    };

    ldtile(sb, Qg + (rb + t0) * DD + h * HD);  // Q joins group 0
    load_kv(0, 0);
    load_kv(1, 1);

    float oacc[8][4] = {};
    float mrow[2] = {-1e30f, -1e30f}, lsum[2] = {0.f, 0.f};
    uint32_t qa[4][4];
    bool qloaded = false;

    for (int blk = 0; blk < 16; blk++) {
        const int cur = blk % 3;
        if (blk + 1 < 16)
            asm volatile("cp.async.wait_group 1;" ::: "memory");
        else
            asm volatile("cp.async.wait_group 0;" ::: "memory");
        __syncthreads();

        if (blk + 2 < 16) load_kv((blk + 2) % 3, blk + 2);

        if (!qloaded) {
            qloaded = true;
#pragma unroll
            for (int ks = 0; ks < 4; ks++)
                ldm_x4(sb + SWZ((warp_m + lrow) * 128 + (ks << 5) + lbyte), qa[ks]);
        }

        float sacc[16][4];
#pragma unroll
        for (int i = 0; i < 16; i++) {
            sacc[i][0] = 0.f; sacc[i][1] = 0.f; sacc[i][2] = 0.f; sacc[i][3] = 0.f;
        }
        // S = Q K^T
#pragma unroll
        for (int s8 = 0; s8 < 8; s8++) {
#pragma unroll
            for (int ks = 0; ks < 4; ks++) {
                uint32_t kf[4];
                ldm_x4(Ks(cur) + SWZ(((s8 << 4) + lrow) * 128 + (ks << 5) + lbyte), kf);
                mma_f16(sacc[2 * s8],     qa[ks], kf[0], kf[2]);
                mma_f16(sacc[2 * s8 + 1], qa[ks], kf[1], kf[3]);
            }
        }
        // online softmax
#pragma unroll
        for (int r = 0; r < 2; r++) {
            float mx = sacc[0][2 * r];
#pragma unroll
            for (int ni = 0; ni < 16; ni++)
                mx = fmaxf(mx, fmaxf(sacc[ni][2 * r], sacc[ni][2 * r + 1]));
            mx = fmaxf(mx, __shfl_xor_sync(0xffffffffu, mx, 1));
            mx = fmaxf(mx, __shfl_xor_sync(0xffffffffu, mx, 2));
            const float mn = fmaxf(mrow[r], mx);
            const float al = fexp(mrow[r] - mn);
            mrow[r] = mn;
            float rs = 0.f;
#pragma unroll
            for (int ni = 0; ni < 16; ni++) {
                float p0 = fexp(sacc[ni][2 * r] - mn);
                float p1 = fexp(sacc[ni][2 * r + 1] - mn);
                sacc[ni][2 * r] = p0; sacc[ni][2 * r + 1] = p1;
                rs += p0 + p1;
            }
            rs += __shfl_xor_sync(0xffffffffu, rs, 1);
            rs += __shfl_xor_sync(0xffffffffu, rs, 2);
            lsum[r] = lsum[r] * al + rs;
#pragma unroll
            for (int nj = 0; nj < 8; nj++) {
                oacc[nj][2 * r] *= al; oacc[nj][2 * r + 1] *= al;
            }
        }
        // O += P V (single-pass fp16)
#pragma unroll
        for (int ks = 0; ks < 8; ks++) {
            uint32_t pa[4];
#pragma unroll
            for (int q = 0; q < 2; q++) {
                const float* c = sacc[2 * ks + q];
                pa[2 * q]     = packh2(c[0], c[1]);
                pa[2 * q + 1] = packh2(c[2], c[3]);
            }
#pragma unroll
            for (int hq = 0; hq < 4; hq++) {
                uint32_t v4[4];
                ldm_x4t(Vs(cur) + SWZ(((ks << 4) + lrow) * 128 + (hq << 5) + lbyte), v4);
                mma_f16(oacc[2 * hq],     pa, v4[0], v4[1]);
                mma_f16(oacc[2 * hq + 1], pa, v4[2], v4[3]);
            }
        }
    }

    // epilogue: normalize, fp16 out, concat layout
    const float inv0 = 1.f / lsum[0], inv1 = 1.f / lsum[1];
#pragma unroll
    for (int nj = 0; nj < 8; nj++) {
        const int col = h * HD + (nj << 3) + (tig << 1);
        const size_t r0 = (rb + t0 + warp_m + gid) * DD + col;
        const size_t r1 = r0 + (size_t)8 * DD;
        *(uint32_t*)&Og[r0] = packh2(oacc[nj][0] * inv0, oacc[nj][1] * inv0);
        *(uint32_t*)&Og[r1] = packh2(oacc[nj][2] * inv1, oacc[nj][3] * inv1);
    }
}

// ---------------- launcher ----------------
extern "C" void kernel_launch(void* const* d_in, const int* in_sizes, int n_in,
                              void* d_out, int out_size)
{
    const float* x  = (const float*)d_in[0];
    const float* Wq = (const float*)d_in[1];
    const float* Wk = (const float*)d_in[2];
    const float* Wv = (const float*)d_in[3];
    const float* Wo = (const float*)d_in[4];
    const float* bo = (const float*)d_in[5];
    float* out = (float*)d_out;

    __half *x16, *w16, *q16, *k16, *v16, *o16;
    cudaGetSymbolAddress((void**)&x16, g_x16);
    cudaGetSymbolAddress((void**)&w16, g_w16);
    cudaGetSymbolAddress((void**)&q16, g_q16);
    cudaGetSymbolAddress((void**)&k16, g_k16);
    cudaGetSymbolAddress((void**)&v16, g_v16);
    cudaGetSymbolAddress((void**)&o16, g_o16);

    cudaFuncSetAttribute(gemm16<0>, cudaFuncAttributeMaxDynamicSharedMemorySize, GEMM_SMEM);
    cudaFuncSetAttribute(gemm16<1>, cudaFuncAttributeMaxDynamicSharedMemorySize, GEMM_SMEM);
    cudaFuncSetAttribute(flash_mma, cudaFuncAttributeMaxDynamicSharedMemorySize, FLASH_SMEM);

    const int n4x = MROWS * DD / 4;
    const int n4w = DD * DD / 4;
    cvt16<<<n4x / 256, 256>>>(x, x16, n4x);
    cvt16w<<<dim3(n4w / 256, 4), 256>>>(Wq, Wk, Wv, Wo, w16);

    dim3 gg(DD / 128, MROWS / 128);  // (8, 64)
    gemm16<1><<<gg, 256, GEMM_SMEM>>>(x16, w16,                       nullptr, q16, nullptr, 0.125f);
    gemm16<1><<<gg, 256, GEMM_SMEM>>>(x16, w16 + (size_t)DD * DD,     nullptr, k16, nullptr, 1.0f);
    gemm16<1><<<gg, 256, GEMM_SMEM>>>(x16, w16 + 2 * (size_t)DD * DD, nullptr, v16, nullptr, 1.0f);

    flash_mma<<<dim3(TT / 128, BB * HH), 256, FLASH_SMEM>>>(q16, k16, v16, o16);

    gemm16<0><<<gg, 256, GEMM_SMEM>>>(o16, w16 + 3 * (size_t)DD * DD, out, nullptr, bo, 1.0f);
}